// round 7
// baseline (speedup 1.0000x reference)
#include <cuda_runtime.h>

// CorrTorch 3D correlation, max_displacement=1.
// in1, in2: [1, 64, 64, 128, 128] fp32; out: [1, 27, 64, 128, 128] fp32.
//
// R6 -> R7: keep R5's instruction diet (halo-product deferral + fma.rn.f32x2)
// and R4's stable 2-stage pipeline, but buy latency hiding with WARPS instead
// of registers: launch_bounds(96,10) caps regs at 68 -> ~30 warps/SM (47% occ)
// vs 25 at 80 regs. (R6 post-mortem: ptxas collapsed the 3-stage ring; the RF
// is per-SM 64K regs, so the reg->MLP trade was strictly worse than reg->occ.)

namespace {
constexpr int C  = 64;
constexpr int DD = 64;
constexpr int HH = 128;
constexpr int WW = 128;
constexpr int HW = HH * WW;        // 16384
constexpr int CS = DD * HW;        // 1048576
constexpr int TPX = 32;            // one warp in x = one full W row
constexpr int NBLK = DD * HH * (WW / 4) / TPX;   // 8192
}

using u64 = unsigned long long;

__device__ __forceinline__ void fma2(u64& d, u64 a, u64 b) {
    asm("fma.rn.f32x2 %0, %1, %2, %0;" : "+l"(d) : "l"(a), "l"(b));
}
__device__ __forceinline__ u64 pack2(float lo, float hi) {
    u64 r; asm("mov.b64 %0, {%1, %2};" : "=l"(r) : "f"(lo), "f"(hi)); return r;
}
__device__ __forceinline__ float2 unpack2(u64 v) {
    float2 r; asm("mov.b64 {%0, %1}, %2;" : "=f"(r.x), "=f"(r.y) : "l"(v)); return r;
}

struct Acc {
    u64   d1a[3], d1b[3];   // dx=1: (out0,out1), (out2,out3)
    u64   d0m[3];           // dx=0: (out1,out2)
    float d0e[3];           // dx=0: out3
    float X[3];             // dx=0: halo sum -> right neighbor's out0
    u64   d2m[3];           // dx=2: (out1,out2)
    float d2e[3];           // dx=2: out0
    float Y[3];             // dx=2: halo sum -> left neighbor's out3
};

__device__ __forceinline__ void ld_stage(const float* __restrict__ q1,
                                         const float* __restrict__ q2,
                                         const bool rv[3],
                                         ulonglong2& a2, ulonglong2 rm[3])
{
    a2 = *reinterpret_cast<const ulonglong2*>(q1);
#pragma unroll
    for (int dy = 0; dy < 3; dy++) {
        if (rv[dy]) rm[dy] = *reinterpret_cast<const ulonglong2*>(q2 + dy * WW);
        else        { rm[dy].x = 0ull; rm[dy].y = 0ull; }
    }
}

__device__ __forceinline__ void do_compute(const ulonglong2& a2,
                                           const ulonglong2 rm[3], Acc& A)
{
    float2 aL = unpack2(a2.x);   // a0, a1
    float2 aH = unpack2(a2.y);   // a2, a3
    u64 A12 = pack2(aL.y, aH.x); // (a1, a2)
    float an0 = __shfl_down_sync(0xffffffffu, aL.x, 1);  // right lane's a0
    float ap3 = __shfl_up_sync  (0xffffffffu, aH.y, 1);  // left lane's a3
#pragma unroll
    for (int dy = 0; dy < 3; dy++) {
        float2 rL = unpack2(rm[dy].x);  // r0, r1
        float2 rH = unpack2(rm[dy].y);  // r2, r3
        fma2(A.d1a[dy], a2.x, rm[dy].x);            // dx=1, out0/1
        fma2(A.d1b[dy], a2.y, rm[dy].y);            // dx=1, out2/3
        fma2(A.d0m[dy], A12, rm[dy].x);             // dx=0, out1/2
        A.d0e[dy] = fmaf(aH.y, rH.x, A.d0e[dy]);    // dx=0, out3
        A.X[dy]   = fmaf(an0, rH.y, A.X[dy]);       // dx=0, deferred halo
        fma2(A.d2m[dy], A12, rm[dy].y);             // dx=2, out1/2
        A.d2e[dy] = fmaf(aL.x, rL.y, A.d2e[dy]);    // dx=2, out0
        A.Y[dy]   = fmaf(ap3, rL.x, A.Y[dy]);       // dx=2, deferred halo
    }
}

__global__ void __launch_bounds__(TPX * 3, 10) corr3d_kernel(
    const float* __restrict__ in1,
    const float* __restrict__ in2,
    float* __restrict__ out)
{
    const int s  = blockIdx.x * TPX + threadIdx.x;  // strip id
    const int dz = threadIdx.y;                     // 0..2
    const int lane = threadIdx.x & 31;
    const int w0 = (s & 31) << 2;                   // 0,4,...,124
    const int h  = (s >> 5) & 127;
    const int d  = s >> 12;

    const int zp = d + dz - 1;                      // in2 source plane
    const bool pz = (zp >= 0) && (zp < DD);
    const bool rv[3] = { pz && (h > 0), pz, pz && (h < HH - 1) };
    const bool pw0 = (lane > 0);
    const bool pw5 = (lane < 31);

    const float* q1 = in1 + d * HW + h * WW + w0;
    const float* q2 = in2 + zp * HW + (h - 1) * WW + w0;

    Acc A;
#pragma unroll
    for (int dy = 0; dy < 3; dy++) {
        A.d1a[dy] = 0; A.d1b[dy] = 0; A.d0m[dy] = 0; A.d2m[dy] = 0;
        A.d0e[dy] = 0.f; A.X[dy] = 0.f; A.d2e[dy] = 0.f; A.Y[dy] = 0.f;
    }

    ulonglong2 aA, aB;
    ulonglong2 rmA[3], rmB[3];

    ld_stage(q1, q2, rv, aA, rmA);                  // c = 0

#pragma unroll 2
    for (int c = 0; c < C - 2; c += 2) {
        q1 += CS; q2 += CS;
        ld_stage(q1, q2, rv, aB, rmB);              // c+1 in flight
        do_compute(aA, rmA, A);                     // consume c
        q1 += CS; q2 += CS;
        ld_stage(q1, q2, rv, aA, rmA);              // c+2 in flight
        do_compute(aB, rmB, A);                     // consume c+1
    }
    q1 += CS; q2 += CS;
    ld_stage(q1, q2, rv, aB, rmB);                  // c = C-1
    do_compute(aA, rmA, A);
    do_compute(aB, rmB, A);

    float* op = out + (long)(dz * 9) * CS + d * HW + h * WW + w0;
    const float inv = 1.0f / 64.0f;
#pragma unroll
    for (int dy = 0; dy < 3; dy++) {
        float xin = __shfl_up_sync(0xffffffffu, A.X[dy], 1);
        float2 m0 = unpack2(A.d0m[dy]);
        float4 v0 = make_float4(pw0 ? xin * inv : 0.f,
                                m0.x * inv, m0.y * inv, A.d0e[dy] * inv);
        *reinterpret_cast<float4*>(op + (long)(dy * 3 + 0) * CS) = v0;

        float2 p1 = unpack2(A.d1a[dy]);
        float2 q1v = unpack2(A.d1b[dy]);
        float4 v1 = make_float4(p1.x * inv, p1.y * inv, q1v.x * inv, q1v.y * inv);
        *reinterpret_cast<float4*>(op + (long)(dy * 3 + 1) * CS) = v1;

        float yin = __shfl_down_sync(0xffffffffu, A.Y[dy], 1);
        float2 m2 = unpack2(A.d2m[dy]);
        float4 v2 = make_float4(A.d2e[dy] * inv, m2.x * inv, m2.y * inv,
                                pw5 ? yin * inv : 0.f);
        *reinterpret_cast<float4*>(op + (long)(dy * 3 + 2) * CS) = v2;
    }
}

extern "C" void kernel_launch(void* const* d_in, const int* in_sizes, int n_in,
                              void* d_out, int out_size)
{
    const float* in1 = (const float*)d_in[0];
    const float* in2 = (const float*)d_in[1];
    float* out = (float*)d_out;
    (void)in_sizes; (void)n_in; (void)out_size;

    dim3 blk(TPX, 3);
    corr3d_kernel<<<NBLK, blk>>>(in1, in2, out);
}

// round 9
// speedup vs baseline: 1.1573x; 1.1573x over previous
#include <cuda_runtime.h>

// CorrTorch 3D correlation, max_displacement=1.
// in1, in2: [1, 64, 64, 128, 128] fp32; out: [1, 27, 64, 128, 128] fp32.
//
// R8 resubmit (R8 bench was an infra failure - container died twice; kernel
// never measured). R7 -> R8: revert to the proven R4 skeleton (2-stage
// register pipeline, (64,3)x192-thread blocks, launch_bounds(192,4), scalar
// FMAs -> 50% issue) and remove only its waste: the per-row 6-float
// shifted-window build (6 SHFL + 6 SEL per channel) becomes deferred-halo
// accumulation (2 SHFL of in1 edges per channel, X/Y halo sums resolved by
// one shuffle in the epilogue). Issues/channel ~60 -> ~48 with identical
// loads and FMA count; body still long enough to cover next-stage latency.

namespace {
constexpr int C  = 64;
constexpr int DD = 64;
constexpr int HH = 128;
constexpr int WW = 128;
constexpr int HW = HH * WW;        // 16384
constexpr int CS = DD * HW;        // 1048576
constexpr int TPX = 64;            // 2 warps in x, each = one full W row
constexpr int NBLK = DD * HH * (WW / 4) / TPX;   // 4096
}

struct Acc {
    float d0[3][3];   // dx=0: out1..out3 per dy
    float X[3];       // dx=0: halo sum -> right neighbor's out0
    float d1[3][4];   // dx=1: out0..out3
    float d2[3][3];   // dx=2: out0..out2
    float Y[3];       // dx=2: halo sum -> left neighbor's out3
};

__device__ __forceinline__ void ld_stage(const float* __restrict__ q1,
                                         const float* __restrict__ q2,
                                         const bool rv[3],
                                         float4& a, float4 rm[3])
{
    a = *reinterpret_cast<const float4*>(q1);
#pragma unroll
    for (int dy = 0; dy < 3; dy++) {
        rm[dy] = rv[dy] ? *reinterpret_cast<const float4*>(q2 + dy * WW)
                        : make_float4(0.f, 0.f, 0.f, 0.f);
    }
}

__device__ __forceinline__ void do_compute(const float4& a, const float4 rm[3],
                                           Acc& A)
{
    float an0 = __shfl_down_sync(0xffffffffu, a.x, 1);  // right lane's a0
    float ap3 = __shfl_up_sync  (0xffffffffu, a.w, 1);  // left lane's a3
#pragma unroll
    for (int dy = 0; dy < 3; dy++) {
        const float4 r = rm[dy];
        // dx = 1: out[j] = a[j] * r[j]
        A.d1[dy][0] = fmaf(a.x, r.x, A.d1[dy][0]);
        A.d1[dy][1] = fmaf(a.y, r.y, A.d1[dy][1]);
        A.d1[dy][2] = fmaf(a.z, r.z, A.d1[dy][2]);
        A.d1[dy][3] = fmaf(a.w, r.w, A.d1[dy][3]);
        // dx = 0: out[j] = a[j] * r[j-1], j=1..3; halo (j=0) deferred via X
        A.d0[dy][0] = fmaf(a.y, r.x, A.d0[dy][0]);
        A.d0[dy][1] = fmaf(a.z, r.y, A.d0[dy][1]);
        A.d0[dy][2] = fmaf(a.w, r.z, A.d0[dy][2]);
        A.X[dy]     = fmaf(an0, r.w, A.X[dy]);
        // dx = 2: out[j] = a[j] * r[j+1], j=0..2; halo (j=3) deferred via Y
        A.d2[dy][0] = fmaf(a.x, r.y, A.d2[dy][0]);
        A.d2[dy][1] = fmaf(a.y, r.z, A.d2[dy][1]);
        A.d2[dy][2] = fmaf(a.z, r.w, A.d2[dy][2]);
        A.Y[dy]     = fmaf(ap3, r.x, A.Y[dy]);
    }
}

__global__ void __launch_bounds__(TPX * 3, 4) corr3d_kernel(
    const float* __restrict__ in1,
    const float* __restrict__ in2,
    float* __restrict__ out)
{
    const int s  = blockIdx.x * TPX + threadIdx.x;  // strip id
    const int dz = threadIdx.y;                     // 0..2
    const int lane = threadIdx.x & 31;
    const int w0 = (s & 31) << 2;                   // 0,4,...,124
    const int h  = (s >> 5) & 127;
    const int d  = s >> 12;

    const int zp = d + dz - 1;                      // in2 source plane
    const bool pz = (zp >= 0) && (zp < DD);
    const bool rv[3] = { pz && (h > 0), pz, pz && (h < HH - 1) };
    const bool pw0 = (lane > 0);
    const bool pw5 = (lane < 31);

    const float* q1 = in1 + d * HW + h * WW + w0;
    const float* q2 = in2 + zp * HW + (h - 1) * WW + w0;

    Acc A;
#pragma unroll
    for (int dy = 0; dy < 3; dy++) {
        A.d0[dy][0] = A.d0[dy][1] = A.d0[dy][2] = 0.f;
        A.d1[dy][0] = A.d1[dy][1] = A.d1[dy][2] = A.d1[dy][3] = 0.f;
        A.d2[dy][0] = A.d2[dy][1] = A.d2[dy][2] = 0.f;
        A.X[dy] = 0.f; A.Y[dy] = 0.f;
    }

    float4 aA, aB;
    float4 rmA[3], rmB[3];

    ld_stage(q1, q2, rv, aA, rmA);                  // c = 0

#pragma unroll 2
    for (int c = 0; c < C - 2; c += 2) {
        q1 += CS; q2 += CS;
        ld_stage(q1, q2, rv, aB, rmB);              // c+1 in flight
        do_compute(aA, rmA, A);                     // consume c
        q1 += CS; q2 += CS;
        ld_stage(q1, q2, rv, aA, rmA);              // c+2 in flight
        do_compute(aB, rmB, A);                     // consume c+1
    }
    q1 += CS; q2 += CS;
    ld_stage(q1, q2, rv, aB, rmB);                  // c = C-1
    do_compute(aA, rmA, A);
    do_compute(aB, rmB, A);

    float* op = out + (long)(dz * 9) * CS + d * HW + h * WW + w0;
    const float inv = 1.0f / 64.0f;
#pragma unroll
    for (int dy = 0; dy < 3; dy++) {
        // dx = 0: out0 comes from the left neighbor's X
        float xin = __shfl_up_sync(0xffffffffu, A.X[dy], 1);
        float4 v0 = make_float4(pw0 ? xin * inv : 0.f,
                                A.d0[dy][0] * inv, A.d0[dy][1] * inv,
                                A.d0[dy][2] * inv);
        *reinterpret_cast<float4*>(op + (long)(dy * 3 + 0) * CS) = v0;
        // dx = 1
        float4 v1 = make_float4(A.d1[dy][0] * inv, A.d1[dy][1] * inv,
                                A.d1[dy][2] * inv, A.d1[dy][3] * inv);
        *reinterpret_cast<float4*>(op + (long)(dy * 3 + 1) * CS) = v1;
        // dx = 2: out3 comes from the right neighbor's Y
        float yin = __shfl_down_sync(0xffffffffu, A.Y[dy], 1);
        float4 v2 = make_float4(A.d2[dy][0] * inv, A.d2[dy][1] * inv,
                                A.d2[dy][2] * inv,
                                pw5 ? yin * inv : 0.f);
        *reinterpret_cast<float4*>(op + (long)(dy * 3 + 2) * CS) = v2;
    }
}

extern "C" void kernel_launch(void* const* d_in, const int* in_sizes, int n_in,
                              void* d_out, int out_size)
{
    const float* in1 = (const float*)d_in[0];
    const float* in2 = (const float*)d_in[1];
    float* out = (float*)d_out;
    (void)in_sizes; (void)n_in; (void)out_size;

    dim3 blk(TPX, 3);
    corr3d_kernel<<<NBLK, blk>>>(in1, in2, out);
}

// round 10
// speedup vs baseline: 1.4322x; 1.2375x over previous
#include <cuda_runtime.h>

// CorrTorch 3D correlation, max_displacement=1.
// in1, in2: [1, 64, 64, 128, 128] fp32; out: [1, 27, 64, 128, 128] fp32.
//
// R9 -> R10: single-variable fix of the R8 regression. R8's measured +30% L1
// cycles / +60% fma-pipe cycles vs R4 (identical C-level loads & FMA count)
// points at ptxas splitting the float4 loads under the deferred-halo reg
// pressure. This round forces LDG.128 via inline PTX (predicated,
// pre-zeroed, ld.global.nc.v4.f32, volatile to pin pipeline placement).
// Everything else is identical to R8: 2-stage pipeline, (64,3)x192 blocks,
// launch_bounds(192,4), deferred-halo compute (36 FMA + 2 SHFL per channel).

namespace {
constexpr int C  = 64;
constexpr int DD = 64;
constexpr int HH = 128;
constexpr int WW = 128;
constexpr int HW = HH * WW;        // 16384
constexpr int CS = DD * HW;        // 1048576
constexpr int TPX = 64;            // 2 warps in x, each = one full W row
constexpr int NBLK = DD * HH * (WW / 4) / TPX;   // 4096
}

__device__ __forceinline__ float4 ldg128(const float* p) {
    float4 v;
    asm volatile("ld.global.nc.v4.f32 {%0,%1,%2,%3}, [%4];"
                 : "=f"(v.x), "=f"(v.y), "=f"(v.z), "=f"(v.w)
                 : "l"(p));
    return v;
}

__device__ __forceinline__ float4 ldg128_pred(const float* p, int pred) {
    float4 v;
    asm volatile("{\n\t"
        ".reg .pred q;\n\t"
        "setp.ne.s32 q, %5, 0;\n\t"
        "mov.f32 %0, 0f00000000;\n\t"
        "mov.f32 %1, 0f00000000;\n\t"
        "mov.f32 %2, 0f00000000;\n\t"
        "mov.f32 %3, 0f00000000;\n\t"
        "@q ld.global.nc.v4.f32 {%0,%1,%2,%3}, [%4];\n\t"
        "}"
        : "=f"(v.x), "=f"(v.y), "=f"(v.z), "=f"(v.w)
        : "l"(p), "r"(pred));
    return v;
}

struct Acc {
    float d0[3][3];   // dx=0: out1..out3 per dy
    float X[3];       // dx=0: halo sum -> right neighbor's out0
    float d1[3][4];   // dx=1: out0..out3
    float d2[3][3];   // dx=2: out0..out2
    float Y[3];       // dx=2: halo sum -> left neighbor's out3
};

__device__ __forceinline__ void ld_stage(const float* __restrict__ q1,
                                         const float* __restrict__ q2,
                                         const int rv[3],
                                         float4& a, float4 rm[3])
{
    a = ldg128(q1);
#pragma unroll
    for (int dy = 0; dy < 3; dy++) {
        rm[dy] = ldg128_pred(q2 + dy * WW, rv[dy]);
    }
}

__device__ __forceinline__ void do_compute(const float4& a, const float4 rm[3],
                                           Acc& A)
{
    float an0 = __shfl_down_sync(0xffffffffu, a.x, 1);  // right lane's a0
    float ap3 = __shfl_up_sync  (0xffffffffu, a.w, 1);  // left lane's a3
#pragma unroll
    for (int dy = 0; dy < 3; dy++) {
        const float4 r = rm[dy];
        // dx = 1: out[j] = a[j] * r[j]
        A.d1[dy][0] = fmaf(a.x, r.x, A.d1[dy][0]);
        A.d1[dy][1] = fmaf(a.y, r.y, A.d1[dy][1]);
        A.d1[dy][2] = fmaf(a.z, r.z, A.d1[dy][2]);
        A.d1[dy][3] = fmaf(a.w, r.w, A.d1[dy][3]);
        // dx = 0: out[j] = a[j] * r[j-1], j=1..3; halo (j=0) deferred via X
        A.d0[dy][0] = fmaf(a.y, r.x, A.d0[dy][0]);
        A.d0[dy][1] = fmaf(a.z, r.y, A.d0[dy][1]);
        A.d0[dy][2] = fmaf(a.w, r.z, A.d0[dy][2]);
        A.X[dy]     = fmaf(an0, r.w, A.X[dy]);
        // dx = 2: out[j] = a[j] * r[j+1], j=0..2; halo (j=3) deferred via Y
        A.d2[dy][0] = fmaf(a.x, r.y, A.d2[dy][0]);
        A.d2[dy][1] = fmaf(a.y, r.z, A.d2[dy][1]);
        A.d2[dy][2] = fmaf(a.z, r.w, A.d2[dy][2]);
        A.Y[dy]     = fmaf(ap3, r.x, A.Y[dy]);
    }
}

__global__ void __launch_bounds__(TPX * 3, 4) corr3d_kernel(
    const float* __restrict__ in1,
    const float* __restrict__ in2,
    float* __restrict__ out)
{
    const int s  = blockIdx.x * TPX + threadIdx.x;  // strip id
    const int dz = threadIdx.y;                     // 0..2
    const int lane = threadIdx.x & 31;
    const int w0 = (s & 31) << 2;                   // 0,4,...,124
    const int h  = (s >> 5) & 127;
    const int d  = s >> 12;

    const int zp = d + dz - 1;                      // in2 source plane
    const int pz = (zp >= 0) && (zp < DD);
    const int rv[3] = { pz && (h > 0), pz, pz && (h < HH - 1) };
    const bool pw0 = (lane > 0);
    const bool pw5 = (lane < 31);

    const float* q1 = in1 + d * HW + h * WW + w0;
    const float* q2 = in2 + zp * HW + (h - 1) * WW + w0;

    Acc A;
#pragma unroll
    for (int dy = 0; dy < 3; dy++) {
        A.d0[dy][0] = A.d0[dy][1] = A.d0[dy][2] = 0.f;
        A.d1[dy][0] = A.d1[dy][1] = A.d1[dy][2] = A.d1[dy][3] = 0.f;
        A.d2[dy][0] = A.d2[dy][1] = A.d2[dy][2] = 0.f;
        A.X[dy] = 0.f; A.Y[dy] = 0.f;
    }

    float4 aA, aB;
    float4 rmA[3], rmB[3];

    ld_stage(q1, q2, rv, aA, rmA);                  // c = 0

#pragma unroll 2
    for (int c = 0; c < C - 2; c += 2) {
        q1 += CS; q2 += CS;
        ld_stage(q1, q2, rv, aB, rmB);              // c+1 in flight
        do_compute(aA, rmA, A);                     // consume c
        q1 += CS; q2 += CS;
        ld_stage(q1, q2, rv, aA, rmA);              // c+2 in flight
        do_compute(aB, rmB, A);                     // consume c+1
    }
    q1 += CS; q2 += CS;
    ld_stage(q1, q2, rv, aB, rmB);                  // c = C-1
    do_compute(aA, rmA, A);
    do_compute(aB, rmB, A);

    float* op = out + (long)(dz * 9) * CS + d * HW + h * WW + w0;
    const float inv = 1.0f / 64.0f;
#pragma unroll
    for (int dy = 0; dy < 3; dy++) {
        // dx = 0: out0 comes from the left neighbor's X
        float xin = __shfl_up_sync(0xffffffffu, A.X[dy], 1);
        float4 v0 = make_float4(pw0 ? xin * inv : 0.f,
                                A.d0[dy][0] * inv, A.d0[dy][1] * inv,
                                A.d0[dy][2] * inv);
        *reinterpret_cast<float4*>(op + (long)(dy * 3 + 0) * CS) = v0;
        // dx = 1
        float4 v1 = make_float4(A.d1[dy][0] * inv, A.d1[dy][1] * inv,
                                A.d1[dy][2] * inv, A.d1[dy][3] * inv);
        *reinterpret_cast<float4*>(op + (long)(dy * 3 + 1) * CS) = v1;
        // dx = 2: out3 comes from the right neighbor's Y
        float yin = __shfl_down_sync(0xffffffffu, A.Y[dy], 1);
        float4 v2 = make_float4(A.d2[dy][0] * inv, A.d2[dy][1] * inv,
                                A.d2[dy][2] * inv,
                                pw5 ? yin * inv : 0.f);
        *reinterpret_cast<float4*>(op + (long)(dy * 3 + 2) * CS) = v2;
    }
}

extern "C" void kernel_launch(void* const* d_in, const int* in_sizes, int n_in,
                              void* d_out, int out_size)
{
    const float* in1 = (const float*)d_in[0];
    const float* in2 = (const float*)d_in[1];
    float* out = (float*)d_out;
    (void)in_sizes; (void)n_in; (void)out_size;

    dim3 blk(TPX, 3);
    corr3d_kernel<<<NBLK, blk>>>(in1, in2, out);
}